// round 14
// baseline (speedup 1.0000x reference)
#include <cuda_runtime.h>
#include <cstdint>

#define EPSV 1e-5f
constexpr int BB = 32, CIN = 240, C1 = 24, HH = 56, WWD = 56, HW = 3136;
constexpr int OUP = 240;
constexpr int KQ = 60;                 // K quarter size

// Scratch — __device__ globals per allocation rules.
__device__ float g_p0[BB * C1 * HW];
__device__ float g_p1[BB * C1 * HW];
__device__ float g_p2[BB * C1 * HW];
__device__ float g_p3[BB * C1 * HW];
__device__ float g_s2[BB * C1 * HW];   // after dw3x3 + bn2 (== x1)
__device__ float* const g_parts[4] = {g_p0, g_p1, g_p2, g_p3};

using u64 = unsigned long long;

__device__ __forceinline__ u64 pk2(float lo, float hi) {
    u64 r; asm("mov.b64 %0, {%1,%2};" : "=l"(r) : "f"(lo), "f"(hi)); return r;
}
__device__ __forceinline__ float2 up2(u64 v) {
    float2 f; asm("mov.b64 {%0,%1}, %2;" : "=f"(f.x), "=f"(f.y) : "l"(v)); return f;
}
__device__ __forceinline__ u64 fma2(u64 a, u64 b, u64 c) {
    u64 d; asm("fma.rn.f32x2 %0, %1, %2, %3;" : "=l"(d) : "l"(a), "l"(b), "l"(c)); return d;
}
__device__ __forceinline__ u64 add2(u64 a, u64 b) {
    u64 d; asm("add.rn.f32x2 %0, %1, %2;" : "=l"(d) : "l"(a), "l"(b)); return d;
}

// ---------------------------------------------------------------------------
// Kernel A: R12/R13 dataflow, reg-capped to 73 (7 CTAs/SM = 28 warps).
// grid (196 px-tiles, 2 ch-halves, 4 K-quarters) = 1568 CTAs, 128 thr.
// L1 floor ~24us, fma floor ~17us; extra warps close the latency gap.
// ---------------------------------------------------------------------------
__global__ __launch_bounds__(128, 7) void kA(
    const float* __restrict__ x, const float* __restrict__ w) {
    __shared__ u64 ws[KQ * 12];             // [k][c] = {w,w}, 5.76 KB
    int tid = threadIdx.x;
    int chb = blockIdx.y * 12;              // channel half base
    int kbase = blockIdx.z * KQ;            // K quarter base
    for (int i = tid; i < KQ * 12; i += 128) {
        int k = i / 12, cc = i % 12;
        float wv = w[(chb + cc) * CIN + kbase + k];
        ws[i] = pk2(wv, wv);
    }
    __syncthreads();

    int p0 = (blockIdx.x * 128 + tid) * 4;  // 4 contiguous px, HW%4==0
    int b = p0 / HW;
    int s = p0 - b * HW;
    const float* xp = x + (size_t)b * CIN * HW + (size_t)kbase * HW + s;

    u64 acc0[12], acc1[12];
#pragma unroll
    for (int c = 0; c < 12; c++) { acc0[c] = 0ull; acc1[c] = 0ull; }

    float4 cur0 = *reinterpret_cast<const float4*>(xp);
    float4 cur1 = *reinterpret_cast<const float4*>(xp + HW);
#pragma unroll 2
    for (int k0 = 0; k0 < KQ; k0 += 2) {
        int kn = (k0 + 2 == KQ) ? 0 : (k0 + 2);   // clamp: redundant L1 hit
        float4 n0 = *reinterpret_cast<const float4*>(xp + (size_t)kn * HW);
        float4 n1 = *reinterpret_cast<const float4*>(xp + (size_t)(kn + 1) * HW);
        {
            u64 xa = pk2(cur0.x, cur0.y);
            u64 xb = pk2(cur0.z, cur0.w);
            const u64* wk = ws + k0 * 12;
#pragma unroll
            for (int c = 0; c < 12; c++) {
                u64 wv = wk[c];
                acc0[c] = fma2(xa, wv, acc0[c]);
                acc1[c] = fma2(xb, wv, acc1[c]);
            }
        }
        {
            u64 xa = pk2(cur1.x, cur1.y);
            u64 xb = pk2(cur1.z, cur1.w);
            const u64* wk = ws + (k0 + 1) * 12;
#pragma unroll
            for (int c = 0; c < 12; c++) {
                u64 wv = wk[c];
                acc0[c] = fma2(xa, wv, acc0[c]);
                acc1[c] = fma2(xb, wv, acc1[c]);
            }
        }
        cur0 = n0; cur1 = n1;
    }
    float* op = g_parts[blockIdx.z] + ((size_t)b * C1 + chb) * HW + s;
#pragma unroll
    for (int c = 0; c < 12; c++) {
        float2 f0 = up2(acc0[c]), f1 = up2(acc1[c]);
        *reinterpret_cast<float4*>(op + (size_t)c * HW) =
            make_float4(f0.x, f0.y, f1.x, f1.y);
    }
}

// ---------------------------------------------------------------------------
// Kernel B: one block per (b,c) plane (768 blocks x 256 thr) — R13 form.
// Stage 1: float4-vectorized merge of 4 partials + BN1 -> shared plane tile.
// Stage 2: dw3x3 + BN2 with halos from SHARED -> g_s2 + out[:, :24).
// ---------------------------------------------------------------------------
__global__ __launch_bounds__(256) void kB(
    const float* __restrict__ g1, const float* __restrict__ b1,
    const float* __restrict__ m1, const float* __restrict__ v1,
    const float* __restrict__ wdw,
    const float* __restrict__ g2, const float* __restrict__ b2,
    const float* __restrict__ m2, const float* __restrict__ v2,
    float* __restrict__ out) {
    __shared__ float tile[HW];             // 12544 B merged+bn1 plane
    int c = blockIdx.x % C1;
    int b = blockIdx.x / C1;
    int tid = threadIdx.x;
    float iv1 = g1[c] * rsqrtf(v1[c] + EPSV);
    float bi1 = b1[c] - m1[c] * iv1;
    size_t poff = ((size_t)b * C1 + c) * HW;
    const float4* p0 = reinterpret_cast<const float4*>(g_p0 + poff);
    const float4* p1 = reinterpret_cast<const float4*>(g_p1 + poff);
    const float4* p2 = reinterpret_cast<const float4*>(g_p2 + poff);
    const float4* p3 = reinterpret_cast<const float4*>(g_p3 + poff);

    // Stage 1: merge + BN1 into shared (784 float4 slots)
#pragma unroll 1
    for (int i = tid; i < 784; i += 256) {
        float4 a = p0[i], q1 = p1[i], q2 = p2[i], q3 = p3[i];
        float4 o;
        o.x = fmaf((a.x + q1.x) + (q2.x + q3.x), iv1, bi1);
        o.y = fmaf((a.y + q1.y) + (q2.y + q3.y), iv1, bi1);
        o.z = fmaf((a.z + q1.z) + (q2.z + q3.z), iv1, bi1);
        o.w = fmaf((a.w + q1.w) + (q2.w + q3.w), iv1, bi1);
        *reinterpret_cast<float4*>(tile + i * 4) = o;
    }
    __syncthreads();

    // Stage 2: dw3x3 + BN2 from shared
    float wv[9];
#pragma unroll
    for (int t = 0; t < 9; t++) wv[t] = __ldg(wdw + c * 9 + t);
    float iv2 = g2[c] * rsqrtf(v2[c] + EPSV);
    float bi2 = b2[c] - m2[c] * iv2;
    float* outc = out + ((size_t)b * OUP + c) * HW;
    float* s2c = g_s2 + poff;

#pragma unroll 1
    for (int q = tid; q < 784; q += 256) {
        int h = q / 14;
        int w0 = (q % 14) * 4;
        float rb[3][6];
#pragma unroll
        for (int dy = 0; dy < 3; dy++) {
            int hh = h + dy - 1;
            bool hok = (hh >= 0) && (hh < HH);
#pragma unroll
            for (int jx = 0; jx < 6; jx++) {
                int ww = w0 + jx - 1;
                rb[dy][jx] = (hok && ww >= 0 && ww < WWD)
                               ? tile[hh * WWD + ww] : 0.0f;
            }
        }
        float acc[4] = {0.f, 0.f, 0.f, 0.f};
#pragma unroll
        for (int dy = 0; dy < 3; dy++)
#pragma unroll
            for (int dx = 0; dx < 3; dx++) {
                float t = wv[dy * 3 + dx];
#pragma unroll
                for (int j = 0; j < 4; j++)
                    acc[j] = fmaf(rb[dy][dx + j], t, acc[j]);
            }
        float4 o = make_float4(fmaf(acc[0], iv2, bi2), fmaf(acc[1], iv2, bi2),
                               fmaf(acc[2], iv2, bi2), fmaf(acc[3], iv2, bi2));
        *reinterpret_cast<float4*>(s2c + h * WWD + w0) = o;
        *reinterpret_cast<float4*>(outc + h * WWD + w0) = o;
    }
}

// ---------------------------------------------------------------------------
// Kernel C: adder depthwise (24 -> 216) + BN3 + ReLU into out channels [24,240).
// One q (4px) per thread, grid (7, 24, 32) x 128. Reads g_s2 from L2.
// Reg-capped to 85 (6 CTAs/SM = 24 warps) — latency-bound, needs warps.
// ---------------------------------------------------------------------------
__global__ __launch_bounds__(128, 6) void kC(
    const float* __restrict__ wadd,
    const float* __restrict__ g3, const float* __restrict__ b3,
    const float* __restrict__ m3, const float* __restrict__ v3,
    float* __restrict__ out) {
    int c = blockIdx.y;
    int b = blockIdx.z;
    __shared__ u64 negtap[81];
    __shared__ float sninv[9], sbias[9];
    int tid = threadIdx.x;
    if (tid < 81) {
        float tv = wadd[c * 81 + tid];
        negtap[tid] = pk2(-tv, -tv);
    }
    if (tid < 9) {
        int ch = c * 9 + tid;
        float iv = g3[ch] * rsqrtf(v3[ch] + EPSV);
        sninv[tid] = -iv;
        sbias[tid] = b3[ch] - m3[ch] * iv;
    }
    __syncthreads();
    int q = blockIdx.x * 128 + tid;
    if (q >= 784) return;
    int h = q / 14;
    int w0 = (q % 14) * 4;
    const float* p = g_s2 + ((size_t)b * C1 + c) * HW;

    float rb[3][6];
#pragma unroll
    for (int dy = 0; dy < 3; dy++) {
        int hh = h + dy - 1;
        bool hok = (hh >= 0) && (hh < HH);
#pragma unroll
        for (int jx = 0; jx < 6; jx++) {
            int ww = w0 + jx - 1;
            rb[dy][jx] = (hok && ww >= 0 && ww < WWD) ? p[hh * WWD + ww] : 0.0f;
        }
    }
    u64 nA[9], nB[9];
#pragma unroll
    for (int dy = 0; dy < 3; dy++)
#pragma unroll
        for (int dx = 0; dx < 3; dx++) {
            nA[dy * 3 + dx] = pk2(rb[dy][dx],     rb[dy][dx + 1]);
            nB[dy * 3 + dx] = pk2(rb[dy][dx + 2], rb[dy][dx + 3]);
        }
    size_t obase = ((size_t)b * OUP + C1 + c * 9) * HW + h * WWD + w0;
#pragma unroll
    for (int r = 0; r < 9; r++) {
        u64 aA = 0ull, aB = 0ull;
#pragma unroll
        for (int t = 0; t < 9; t++) {
            u64 nt = negtap[r * 9 + t];
            u64 dA = add2(nA[t], nt) & 0x7FFFFFFF7FFFFFFFull;
            u64 dB = add2(nB[t], nt) & 0x7FFFFFFF7FFFFFFFull;
            aA = add2(aA, dA);
            aB = add2(aB, dB);
        }
        float2 fa = up2(aA), fb = up2(aB);
        float ni = sninv[r], bi = sbias[r];
        float4 o = make_float4(fmaxf(fmaf(fa.x, ni, bi), 0.f),
                               fmaxf(fmaf(fa.y, ni, bi), 0.f),
                               fmaxf(fmaf(fb.x, ni, bi), 0.f),
                               fmaxf(fmaf(fb.y, ni, bi), 0.f));
        *reinterpret_cast<float4*>(out + obase + (size_t)r * HW) = o;
    }
}

extern "C" void kernel_launch(void* const* d_in, const int* in_sizes, int n_in,
                              void* d_out, int out_size) {
    const float* x   = (const float*)d_in[0];
    const float* wp  = (const float*)d_in[1];
    const float* g1  = (const float*)d_in[2];
    const float* b1  = (const float*)d_in[3];
    const float* m1  = (const float*)d_in[4];
    const float* v1  = (const float*)d_in[5];
    const float* wdw = (const float*)d_in[6];
    const float* g2  = (const float*)d_in[7];
    const float* b2  = (const float*)d_in[8];
    const float* m2  = (const float*)d_in[9];
    const float* v2  = (const float*)d_in[10];
    const float* wa  = (const float*)d_in[11];
    const float* g3  = (const float*)d_in[12];
    const float* b3  = (const float*)d_in[13];
    const float* m3  = (const float*)d_in[14];
    const float* v3  = (const float*)d_in[15];
    float* out = (float*)d_out;

    kA<<<dim3(196, 2, 4), 128>>>(x, wp);
    kB<<<BB * C1, 256>>>(g1, b1, m1, v1, wdw, g2, b2, m2, v2, out);
    kC<<<dim3(7, 24, 32), 128>>>(wa, g3, b3, m3, v3, out);
}

// round 15
// speedup vs baseline: 1.0894x; 1.0894x over previous
#include <cuda_runtime.h>
#include <cstdint>

#define EPSV 1e-5f
constexpr int BB = 32, CIN = 240, C1 = 24, HH = 56, WWD = 56, HW = 3136;
constexpr int OUP = 240;
constexpr int KQ = 60;                 // K quarter size

// Scratch — __device__ globals per allocation rules.
__device__ float g_p0[BB * C1 * HW];
__device__ float g_p1[BB * C1 * HW];
__device__ float g_p2[BB * C1 * HW];
__device__ float g_p3[BB * C1 * HW];
__device__ float g_s2[BB * C1 * HW];   // after dw3x3 + bn2 (== x1)
__device__ float* const g_parts[4] = {g_p0, g_p1, g_p2, g_p3};

using u64 = unsigned long long;

__device__ __forceinline__ u64 pk2(float lo, float hi) {
    u64 r; asm("mov.b64 %0, {%1,%2};" : "=l"(r) : "f"(lo), "f"(hi)); return r;
}
__device__ __forceinline__ float2 up2(u64 v) {
    float2 f; asm("mov.b64 {%0,%1}, %2;" : "=f"(f.x), "=f"(f.y) : "l"(v)); return f;
}
__device__ __forceinline__ u64 fma2(u64 a, u64 b, u64 c) {
    u64 d; asm("fma.rn.f32x2 %0, %1, %2, %3;" : "=l"(d) : "l"(a), "l"(b), "l"(c)); return d;
}
__device__ __forceinline__ u64 add2(u64 a, u64 b) {
    u64 d; asm("add.rn.f32x2 %0, %1, %2;" : "=l"(d) : "l"(a), "l"(b)); return d;
}

// ---------------------------------------------------------------------------
// Kernel A: R13 exact (best measured: 46.0us).
// grid (196 px-tiles, 2 ch-halves, 4 K-quarters) = 1568 CTAs, 128 thr.
// ---------------------------------------------------------------------------
__global__ __launch_bounds__(128, 6) void kA(
    const float* __restrict__ x, const float* __restrict__ w) {
    __shared__ u64 ws[KQ * 12];             // [k][c] = {w,w}, 5.76 KB
    int tid = threadIdx.x;
    int chb = blockIdx.y * 12;              // channel half base
    int kbase = blockIdx.z * KQ;            // K quarter base
    for (int i = tid; i < KQ * 12; i += 128) {
        int k = i / 12, cc = i % 12;
        float wv = w[(chb + cc) * CIN + kbase + k];
        ws[i] = pk2(wv, wv);
    }
    __syncthreads();

    int p0 = (blockIdx.x * 128 + tid) * 4;  // 4 contiguous px, HW%4==0
    int b = p0 / HW;
    int s = p0 - b * HW;
    const float* xp = x + (size_t)b * CIN * HW + (size_t)kbase * HW + s;

    u64 acc0[12], acc1[12];
#pragma unroll
    for (int c = 0; c < 12; c++) { acc0[c] = 0ull; acc1[c] = 0ull; }

    float4 cur0 = *reinterpret_cast<const float4*>(xp);
    float4 cur1 = *reinterpret_cast<const float4*>(xp + HW);
#pragma unroll 2
    for (int k0 = 0; k0 < KQ; k0 += 2) {
        int kn = (k0 + 2 == KQ) ? 0 : (k0 + 2);   // clamp: redundant L1 hit
        float4 n0 = *reinterpret_cast<const float4*>(xp + (size_t)kn * HW);
        float4 n1 = *reinterpret_cast<const float4*>(xp + (size_t)(kn + 1) * HW);
        {
            u64 xa = pk2(cur0.x, cur0.y);
            u64 xb = pk2(cur0.z, cur0.w);
            const u64* wk = ws + k0 * 12;
#pragma unroll
            for (int c = 0; c < 12; c++) {
                u64 wv = wk[c];
                acc0[c] = fma2(xa, wv, acc0[c]);
                acc1[c] = fma2(xb, wv, acc1[c]);
            }
        }
        {
            u64 xa = pk2(cur1.x, cur1.y);
            u64 xb = pk2(cur1.z, cur1.w);
            const u64* wk = ws + (k0 + 1) * 12;
#pragma unroll
            for (int c = 0; c < 12; c++) {
                u64 wv = wk[c];
                acc0[c] = fma2(xa, wv, acc0[c]);
                acc1[c] = fma2(xb, wv, acc1[c]);
            }
        }
        cur0 = n0; cur1 = n1;
    }
    float* op = g_parts[blockIdx.z] + ((size_t)b * C1 + chb) * HW + s;
#pragma unroll
    for (int c = 0; c < 12; c++) {
        float2 f0 = up2(acc0[c]), f1 = up2(acc1[c]);
        *reinterpret_cast<float4*>(op + (size_t)c * HW) =
            make_float4(f0.x, f0.y, f1.x, f1.y);
    }
}

// ---------------------------------------------------------------------------
// Kernel B: R13 exact. One block per (b,c) plane (768 blocks x 256 thr).
// Stage 1: float4-vectorized merge of 4 partials + BN1 -> shared plane tile.
// Stage 2: dw3x3 + BN2 with halos from SHARED -> g_s2 + out[:, :24).
// ---------------------------------------------------------------------------
__global__ __launch_bounds__(256) void kB(
    const float* __restrict__ g1, const float* __restrict__ b1,
    const float* __restrict__ m1, const float* __restrict__ v1,
    const float* __restrict__ wdw,
    const float* __restrict__ g2, const float* __restrict__ b2,
    const float* __restrict__ m2, const float* __restrict__ v2,
    float* __restrict__ out) {
    __shared__ float tile[HW];             // 12544 B merged+bn1 plane
    int c = blockIdx.x % C1;
    int b = blockIdx.x / C1;
    int tid = threadIdx.x;
    float iv1 = g1[c] * rsqrtf(v1[c] + EPSV);
    float bi1 = b1[c] - m1[c] * iv1;
    size_t poff = ((size_t)b * C1 + c) * HW;
    const float4* p0 = reinterpret_cast<const float4*>(g_p0 + poff);
    const float4* p1 = reinterpret_cast<const float4*>(g_p1 + poff);
    const float4* p2 = reinterpret_cast<const float4*>(g_p2 + poff);
    const float4* p3 = reinterpret_cast<const float4*>(g_p3 + poff);

    // Stage 1: merge + BN1 into shared (784 float4 slots)
#pragma unroll 1
    for (int i = tid; i < 784; i += 256) {
        float4 a = p0[i], q1 = p1[i], q2 = p2[i], q3 = p3[i];
        float4 o;
        o.x = fmaf((a.x + q1.x) + (q2.x + q3.x), iv1, bi1);
        o.y = fmaf((a.y + q1.y) + (q2.y + q3.y), iv1, bi1);
        o.z = fmaf((a.z + q1.z) + (q2.z + q3.z), iv1, bi1);
        o.w = fmaf((a.w + q1.w) + (q2.w + q3.w), iv1, bi1);
        *reinterpret_cast<float4*>(tile + i * 4) = o;
    }
    __syncthreads();

    // Stage 2: dw3x3 + BN2 from shared
    float wv[9];
#pragma unroll
    for (int t = 0; t < 9; t++) wv[t] = __ldg(wdw + c * 9 + t);
    float iv2 = g2[c] * rsqrtf(v2[c] + EPSV);
    float bi2 = b2[c] - m2[c] * iv2;
    float* outc = out + ((size_t)b * OUP + c) * HW;
    float* s2c = g_s2 + poff;

#pragma unroll 1
    for (int q = tid; q < 784; q += 256) {
        int h = q / 14;
        int w0 = (q % 14) * 4;
        float rb[3][6];
#pragma unroll
        for (int dy = 0; dy < 3; dy++) {
            int hh = h + dy - 1;
            bool hok = (hh >= 0) && (hh < HH);
#pragma unroll
            for (int jx = 0; jx < 6; jx++) {
                int ww = w0 + jx - 1;
                rb[dy][jx] = (hok && ww >= 0 && ww < WWD)
                               ? tile[hh * WWD + ww] : 0.0f;
            }
        }
        float acc[4] = {0.f, 0.f, 0.f, 0.f};
#pragma unroll
        for (int dy = 0; dy < 3; dy++)
#pragma unroll
            for (int dx = 0; dx < 3; dx++) {
                float t = wv[dy * 3 + dx];
#pragma unroll
                for (int j = 0; j < 4; j++)
                    acc[j] = fmaf(rb[dy][dx + j], t, acc[j]);
            }
        float4 o = make_float4(fmaf(acc[0], iv2, bi2), fmaf(acc[1], iv2, bi2),
                               fmaf(acc[2], iv2, bi2), fmaf(acc[3], iv2, bi2));
        *reinterpret_cast<float4*>(s2c + h * WWD + w0) = o;
        *reinterpret_cast<float4*>(outc + h * WWD + w0) = o;
    }
}

// ---------------------------------------------------------------------------
// Kernel C: adder depthwise (24 -> 216) + BN3 + ReLU into out channels [24,240).
// Same proven 1-q-per-thread body, but each block STAGES its ~12-row slice of
// the g_s2 plane into shared first (coalesced float4), so all 18 halo taps
// come from smem (29 cyc) instead of L2 (234+ cyc).
// grid (7, 24, 32) x 128.
// ---------------------------------------------------------------------------
__global__ __launch_bounds__(128) void kC(
    const float* __restrict__ wadd,
    const float* __restrict__ g3, const float* __restrict__ b3,
    const float* __restrict__ m3, const float* __restrict__ v3,
    float* __restrict__ out) {
    int c = blockIdx.y;
    int b = blockIdx.z;
    __shared__ float tile[12 * WWD];       // up to 12 staged rows
    __shared__ u64 negtap[81];
    __shared__ float sninv[9], sbias[9];
    int tid = threadIdx.x;
    if (tid < 81) {
        float tv = wadd[c * 81 + tid];
        negtap[tid] = pk2(-tv, -tv);
    }
    if (tid < 9) {
        int ch = c * 9 + tid;
        float iv = g3[ch] * rsqrtf(v3[ch] + EPSV);
        sninv[tid] = -iv;
        sbias[tid] = b3[ch] - m3[ch] * iv;
    }

    int qbase = blockIdx.x * 128;
    int qlast = min(qbase + 127, 783);
    int h_lo = max(qbase / 14 - 1, 0);
    int h_hi = min(qlast / 14 + 1, HH - 1);
    int nrow = h_hi - h_lo + 1;            // <= 12
    const float* p = g_s2 + ((size_t)b * C1 + c) * HW;

    // Stage rows [h_lo, h_hi] into shared, coalesced float4.
    {
        const float4* src = reinterpret_cast<const float4*>(p + h_lo * WWD);
        float4* dst = reinterpret_cast<float4*>(tile);
        int n4 = nrow * 14;                // <= 168
        for (int i = tid; i < n4; i += 128) dst[i] = src[i];
    }
    __syncthreads();

    int q = qbase + tid;
    if (q >= 784) return;
    int h = q / 14;
    int w0 = (q % 14) * 4;

    float rb[3][6];
#pragma unroll
    for (int dy = 0; dy < 3; dy++) {
        int hh = h + dy - 1;
        bool hok = (hh >= 0) && (hh < HH);
        const float* trow = tile + (hh - h_lo) * WWD;
#pragma unroll
        for (int jx = 0; jx < 6; jx++) {
            int ww = w0 + jx - 1;
            rb[dy][jx] = (hok && ww >= 0 && ww < WWD) ? trow[ww] : 0.0f;
        }
    }
    u64 nA[9], nB[9];
#pragma unroll
    for (int dy = 0; dy < 3; dy++)
#pragma unroll
        for (int dx = 0; dx < 3; dx++) {
            nA[dy * 3 + dx] = pk2(rb[dy][dx],     rb[dy][dx + 1]);
            nB[dy * 3 + dx] = pk2(rb[dy][dx + 2], rb[dy][dx + 3]);
        }
    size_t obase = ((size_t)b * OUP + C1 + c * 9) * HW + h * WWD + w0;
#pragma unroll
    for (int r = 0; r < 9; r++) {
        u64 aA = 0ull, aB = 0ull;
#pragma unroll
        for (int t = 0; t < 9; t++) {
            u64 nt = negtap[r * 9 + t];
            u64 dA = add2(nA[t], nt) & 0x7FFFFFFF7FFFFFFFull;
            u64 dB = add2(nB[t], nt) & 0x7FFFFFFF7FFFFFFFull;
            aA = add2(aA, dA);
            aB = add2(aB, dB);
        }
        float2 fa = up2(aA), fb = up2(aB);
        float ni = sninv[r], bi = sbias[r];
        float4 o = make_float4(fmaxf(fmaf(fa.x, ni, bi), 0.f),
                               fmaxf(fmaf(fa.y, ni, bi), 0.f),
                               fmaxf(fmaf(fb.x, ni, bi), 0.f),
                               fmaxf(fmaf(fb.y, ni, bi), 0.f));
        *reinterpret_cast<float4*>(out + obase + (size_t)r * HW) = o;
    }
}

extern "C" void kernel_launch(void* const* d_in, const int* in_sizes, int n_in,
                              void* d_out, int out_size) {
    const float* x   = (const float*)d_in[0];
    const float* wp  = (const float*)d_in[1];
    const float* g1  = (const float*)d_in[2];
    const float* b1  = (const float*)d_in[3];
    const float* m1  = (const float*)d_in[4];
    const float* v1  = (const float*)d_in[5];
    const float* wdw = (const float*)d_in[6];
    const float* g2  = (const float*)d_in[7];
    const float* b2  = (const float*)d_in[8];
    const float* m2  = (const float*)d_in[9];
    const float* v2  = (const float*)d_in[10];
    const float* wa  = (const float*)d_in[11];
    const float* g3  = (const float*)d_in[12];
    const float* b3  = (const float*)d_in[13];
    const float* m3  = (const float*)d_in[14];
    const float* v3  = (const float*)d_in[15];
    float* out = (float*)d_out;

    kA<<<dim3(196, 2, 4), 128>>>(x, wp);
    kB<<<BB * C1, 256>>>(g1, b1, m1, v1, wdw, g2, b2, m2, v2, out);
    kC<<<dim3(7, 24, 32), 128>>>(wa, g3, b3, m3, v3, out);
}

// round 16
// speedup vs baseline: 1.1226x; 1.0305x over previous
#include <cuda_runtime.h>
#include <cstdint>

#define EPSV 1e-5f
constexpr int BB = 32, CIN = 240, C1 = 24, HH = 56, WWD = 56, HW = 3136;
constexpr int OUP = 240;
constexpr int KQ = 60;                 // K quarter size

// Scratch — __device__ globals per allocation rules.
__device__ float g_p0[BB * C1 * HW];
__device__ float g_p1[BB * C1 * HW];
__device__ float g_p2[BB * C1 * HW];
__device__ float g_p3[BB * C1 * HW];
__device__ float g_s2[BB * C1 * HW];   // after dw3x3 + bn2 (== x1)
__device__ float* const g_parts[4] = {g_p0, g_p1, g_p2, g_p3};

using u64 = unsigned long long;

__device__ __forceinline__ u64 pk2(float lo, float hi) {
    u64 r; asm("mov.b64 %0, {%1,%2};" : "=l"(r) : "f"(lo), "f"(hi)); return r;
}
__device__ __forceinline__ float2 up2(u64 v) {
    float2 f; asm("mov.b64 {%0,%1}, %2;" : "=f"(f.x), "=f"(f.y) : "l"(v)); return f;
}
__device__ __forceinline__ u64 fma2(u64 a, u64 b, u64 c) {
    u64 d; asm("fma.rn.f32x2 %0, %1, %2, %3;" : "=l"(d) : "l"(a), "l"(b), "l"(c)); return d;
}
__device__ __forceinline__ u64 add2(u64 a, u64 b) {
    u64 d; asm("add.rn.f32x2 %0, %1, %2;" : "=l"(d) : "l"(a), "l"(b)); return d;
}

// ---------------------------------------------------------------------------
// Kernel A: 1x1 conv raw partial sums — 4-way CHANNEL split for occupancy.
// grid (196 px-tiles, 4 ch-splits of 6, 4 K-quarters) = 3136 CTAs, 128 thr.
// Thread = 4 px x 6 ch: 12 f32x2 accs (24 regs) -> ~60 regs total ->
// 8 CTAs/SM = 32 warps. Per k: 6 LDS.64 + 1 LDG.128 + 12 FFMA2.
// x re-read by co-resident ch-split twins lands in L2 (DRAM unchanged).
// ---------------------------------------------------------------------------
__global__ __launch_bounds__(128, 8) void kA(
    const float* __restrict__ x, const float* __restrict__ w) {
    __shared__ u64 ws[KQ * 6];              // [k][c] = {w,w}, 2.88 KB
    int tid = threadIdx.x;
    int chb = blockIdx.y * 6;               // channel split base
    int kbase = blockIdx.z * KQ;            // K quarter base
    for (int i = tid; i < KQ * 6; i += 128) {
        int k = i / 6, cc = i % 6;
        float wv = w[(chb + cc) * CIN + kbase + k];
        ws[i] = pk2(wv, wv);
    }
    __syncthreads();

    int p0 = (blockIdx.x * 128 + tid) * 4;  // 4 contiguous px, HW%4==0
    int b = p0 / HW;
    int s = p0 - b * HW;
    const float* xp = x + (size_t)b * CIN * HW + (size_t)kbase * HW + s;

    u64 acc0[6], acc1[6];
#pragma unroll
    for (int c = 0; c < 6; c++) { acc0[c] = 0ull; acc1[c] = 0ull; }

    float4 cur0 = *reinterpret_cast<const float4*>(xp);
    float4 cur1 = *reinterpret_cast<const float4*>(xp + HW);
#pragma unroll 2
    for (int k0 = 0; k0 < KQ; k0 += 2) {
        int kn = (k0 + 2 == KQ) ? 0 : (k0 + 2);   // clamp: redundant L1 hit
        float4 n0 = *reinterpret_cast<const float4*>(xp + (size_t)kn * HW);
        float4 n1 = *reinterpret_cast<const float4*>(xp + (size_t)(kn + 1) * HW);
        {
            u64 xa = pk2(cur0.x, cur0.y);
            u64 xb = pk2(cur0.z, cur0.w);
            const u64* wk = ws + k0 * 6;
#pragma unroll
            for (int c = 0; c < 6; c++) {
                u64 wv = wk[c];
                acc0[c] = fma2(xa, wv, acc0[c]);
                acc1[c] = fma2(xb, wv, acc1[c]);
            }
        }
        {
            u64 xa = pk2(cur1.x, cur1.y);
            u64 xb = pk2(cur1.z, cur1.w);
            const u64* wk = ws + (k0 + 1) * 6;
#pragma unroll
            for (int c = 0; c < 6; c++) {
                u64 wv = wk[c];
                acc0[c] = fma2(xa, wv, acc0[c]);
                acc1[c] = fma2(xb, wv, acc1[c]);
            }
        }
        cur0 = n0; cur1 = n1;
    }
    float* op = g_parts[blockIdx.z] + ((size_t)b * C1 + chb) * HW + s;
#pragma unroll
    for (int c = 0; c < 6; c++) {
        float2 f0 = up2(acc0[c]), f1 = up2(acc1[c]);
        *reinterpret_cast<float4*>(op + (size_t)c * HW) =
            make_float4(f0.x, f0.y, f1.x, f1.y);
    }
}

// ---------------------------------------------------------------------------
// Kernel B: R13 exact. One block per (b,c) plane (768 blocks x 256 thr).
// Stage 1: float4-vectorized merge of 4 partials + BN1 -> shared plane tile.
// Stage 2: dw3x3 + BN2 with halos from SHARED -> g_s2 + out[:, :24).
// ---------------------------------------------------------------------------
__global__ __launch_bounds__(256) void kB(
    const float* __restrict__ g1, const float* __restrict__ b1,
    const float* __restrict__ m1, const float* __restrict__ v1,
    const float* __restrict__ wdw,
    const float* __restrict__ g2, const float* __restrict__ b2,
    const float* __restrict__ m2, const float* __restrict__ v2,
    float* __restrict__ out) {
    __shared__ float tile[HW];             // 12544 B merged+bn1 plane
    int c = blockIdx.x % C1;
    int b = blockIdx.x / C1;
    int tid = threadIdx.x;
    float iv1 = g1[c] * rsqrtf(v1[c] + EPSV);
    float bi1 = b1[c] - m1[c] * iv1;
    size_t poff = ((size_t)b * C1 + c) * HW;
    const float4* p0 = reinterpret_cast<const float4*>(g_p0 + poff);
    const float4* p1 = reinterpret_cast<const float4*>(g_p1 + poff);
    const float4* p2 = reinterpret_cast<const float4*>(g_p2 + poff);
    const float4* p3 = reinterpret_cast<const float4*>(g_p3 + poff);

    // Stage 1: merge + BN1 into shared (784 float4 slots)
#pragma unroll 1
    for (int i = tid; i < 784; i += 256) {
        float4 a = p0[i], q1 = p1[i], q2 = p2[i], q3 = p3[i];
        float4 o;
        o.x = fmaf((a.x + q1.x) + (q2.x + q3.x), iv1, bi1);
        o.y = fmaf((a.y + q1.y) + (q2.y + q3.y), iv1, bi1);
        o.z = fmaf((a.z + q1.z) + (q2.z + q3.z), iv1, bi1);
        o.w = fmaf((a.w + q1.w) + (q2.w + q3.w), iv1, bi1);
        *reinterpret_cast<float4*>(tile + i * 4) = o;
    }
    __syncthreads();

    // Stage 2: dw3x3 + BN2 from shared
    float wv[9];
#pragma unroll
    for (int t = 0; t < 9; t++) wv[t] = __ldg(wdw + c * 9 + t);
    float iv2 = g2[c] * rsqrtf(v2[c] + EPSV);
    float bi2 = b2[c] - m2[c] * iv2;
    float* outc = out + ((size_t)b * OUP + c) * HW;
    float* s2c = g_s2 + poff;

#pragma unroll 1
    for (int q = tid; q < 784; q += 256) {
        int h = q / 14;
        int w0 = (q % 14) * 4;
        float rb[3][6];
#pragma unroll
        for (int dy = 0; dy < 3; dy++) {
            int hh = h + dy - 1;
            bool hok = (hh >= 0) && (hh < HH);
#pragma unroll
            for (int jx = 0; jx < 6; jx++) {
                int ww = w0 + jx - 1;
                rb[dy][jx] = (hok && ww >= 0 && ww < WWD)
                               ? tile[hh * WWD + ww] : 0.0f;
            }
        }
        float acc[4] = {0.f, 0.f, 0.f, 0.f};
#pragma unroll
        for (int dy = 0; dy < 3; dy++)
#pragma unroll
            for (int dx = 0; dx < 3; dx++) {
                float t = wv[dy * 3 + dx];
#pragma unroll
                for (int j = 0; j < 4; j++)
                    acc[j] = fmaf(rb[dy][dx + j], t, acc[j]);
            }
        float4 o = make_float4(fmaf(acc[0], iv2, bi2), fmaf(acc[1], iv2, bi2),
                               fmaf(acc[2], iv2, bi2), fmaf(acc[3], iv2, bi2));
        *reinterpret_cast<float4*>(s2c + h * WWD + w0) = o;
        *reinterpret_cast<float4*>(outc + h * WWD + w0) = o;
    }
}

// ---------------------------------------------------------------------------
// Kernel C: R15 exact. Adder depthwise (24 -> 216) + BN3 + ReLU.
// Each block stages its ~12-row slice of g_s2 into shared, halo taps from smem.
// grid (7, 24, 32) x 128.
// ---------------------------------------------------------------------------
__global__ __launch_bounds__(128) void kC(
    const float* __restrict__ wadd,
    const float* __restrict__ g3, const float* __restrict__ b3,
    const float* __restrict__ m3, const float* __restrict__ v3,
    float* __restrict__ out) {
    int c = blockIdx.y;
    int b = blockIdx.z;
    __shared__ float tile[12 * WWD];       // up to 12 staged rows
    __shared__ u64 negtap[81];
    __shared__ float sninv[9], sbias[9];
    int tid = threadIdx.x;
    if (tid < 81) {
        float tv = wadd[c * 81 + tid];
        negtap[tid] = pk2(-tv, -tv);
    }
    if (tid < 9) {
        int ch = c * 9 + tid;
        float iv = g3[ch] * rsqrtf(v3[ch] + EPSV);
        sninv[tid] = -iv;
        sbias[tid] = b3[ch] - m3[ch] * iv;
    }

    int qbase = blockIdx.x * 128;
    int qlast = min(qbase + 127, 783);
    int h_lo = max(qbase / 14 - 1, 0);
    int h_hi = min(qlast / 14 + 1, HH - 1);
    int nrow = h_hi - h_lo + 1;            // <= 12
    const float* p = g_s2 + ((size_t)b * C1 + c) * HW;

    // Stage rows [h_lo, h_hi] into shared, coalesced float4.
    {
        const float4* src = reinterpret_cast<const float4*>(p + h_lo * WWD);
        float4* dst = reinterpret_cast<float4*>(tile);
        int n4 = nrow * 14;                // <= 168
        for (int i = tid; i < n4; i += 128) dst[i] = src[i];
    }
    __syncthreads();

    int q = qbase + tid;
    if (q >= 784) return;
    int h = q / 14;
    int w0 = (q % 14) * 4;

    float rb[3][6];
#pragma unroll
    for (int dy = 0; dy < 3; dy++) {
        int hh = h + dy - 1;
        bool hok = (hh >= 0) && (hh < HH);
        const float* trow = tile + (hh - h_lo) * WWD;
#pragma unroll
        for (int jx = 0; jx < 6; jx++) {
            int ww = w0 + jx - 1;
            rb[dy][jx] = (hok && ww >= 0 && ww < WWD) ? trow[ww] : 0.0f;
        }
    }
    u64 nA[9], nB[9];
#pragma unroll
    for (int dy = 0; dy < 3; dy++)
#pragma unroll
        for (int dx = 0; dx < 3; dx++) {
            nA[dy * 3 + dx] = pk2(rb[dy][dx],     rb[dy][dx + 1]);
            nB[dy * 3 + dx] = pk2(rb[dy][dx + 2], rb[dy][dx + 3]);
        }
    size_t obase = ((size_t)b * OUP + C1 + c * 9) * HW + h * WWD + w0;
#pragma unroll
    for (int r = 0; r < 9; r++) {
        u64 aA = 0ull, aB = 0ull;
#pragma unroll
        for (int t = 0; t < 9; t++) {
            u64 nt = negtap[r * 9 + t];
            u64 dA = add2(nA[t], nt) & 0x7FFFFFFF7FFFFFFFull;
            u64 dB = add2(nB[t], nt) & 0x7FFFFFFF7FFFFFFFull;
            aA = add2(aA, dA);
            aB = add2(aB, dB);
        }
        float2 fa = up2(aA), fb = up2(aB);
        float ni = sninv[r], bi = sbias[r];
        float4 o = make_float4(fmaxf(fmaf(fa.x, ni, bi), 0.f),
                               fmaxf(fmaf(fa.y, ni, bi), 0.f),
                               fmaxf(fmaf(fb.x, ni, bi), 0.f),
                               fmaxf(fmaf(fb.y, ni, bi), 0.f));
        *reinterpret_cast<float4*>(out + obase + (size_t)r * HW) = o;
    }
}

extern "C" void kernel_launch(void* const* d_in, const int* in_sizes, int n_in,
                              void* d_out, int out_size) {
    const float* x   = (const float*)d_in[0];
    const float* wp  = (const float*)d_in[1];
    const float* g1  = (const float*)d_in[2];
    const float* b1  = (const float*)d_in[3];
    const float* m1  = (const float*)d_in[4];
    const float* v1  = (const float*)d_in[5];
    const float* wdw = (const float*)d_in[6];
    const float* g2  = (const float*)d_in[7];
    const float* b2  = (const float*)d_in[8];
    const float* m2  = (const float*)d_in[9];
    const float* v2  = (const float*)d_in[10];
    const float* wa  = (const float*)d_in[11];
    const float* g3  = (const float*)d_in[12];
    const float* b3  = (const float*)d_in[13];
    const float* m3  = (const float*)d_in[14];
    const float* v3  = (const float*)d_in[15];
    float* out = (float*)d_out;

    kA<<<dim3(196, 4, 4), 128>>>(x, wp);
    kB<<<BB * C1, 256>>>(g1, b1, m1, v1, wdw, g2, b2, m2, v2, out);
    kC<<<dim3(7, 24, 32), 128>>>(wa, g3, b3, m3, v3, out);
}